// round 11
// baseline (speedup 1.0000x reference)
#include <cuda_runtime.h>

#define BB 32
#define SS 2048
#define NROWS (BB * SS)
#define NSPLIT 16

// Scratch: __device__ globals (no allocation allowed in kernel_launch).
__device__ float4 g_Q[NROWS];            // pre-scaled by 0.5*log2(e)
// Pair-packed layouts: for key pair p (rows 2p, 2p+1):
//   g_Kp[2p]   = (k0.x, k1.x, k0.y, k1.y)
//   g_Kp[2p+1] = (k0.z, k1.z, k0.w, k1.w)
__device__ float4 g_Kp[NROWS];
__device__ float4 g_Vp[NROWS];
__device__ float4 g_pnum[NSPLIT * NROWS];  // partial sum(e*V)
__device__ float  g_pden[NSPLIT * NROWS];  // partial sum(e)

typedef unsigned long long ull;

// ---------------------------------------------------------------------------
// Packed f32x2 helpers (sm_103a FFMA2 path — ptxas won't auto-fuse from C++)
// ---------------------------------------------------------------------------
__device__ __forceinline__ ull pack2(float lo, float hi) {
    ull r; asm("mov.b64 %0, {%1, %2};" : "=l"(r) : "f"(lo), "f"(hi)); return r;
}
__device__ __forceinline__ void unpack2(ull v, float& lo, float& hi) {
    asm("mov.b64 {%0, %1}, %2;" : "=f"(lo), "=f"(hi) : "l"(v));
}
__device__ __forceinline__ ull fma2(ull a, ull b, ull c) {
    ull d; asm("fma.rn.f32x2 %0, %1, %2, %3;" : "=l"(d) : "l"(a), "l"(b), "l"(c)); return d;
}
__device__ __forceinline__ ull mul2(ull a, ull b) {
    ull d; asm("mul.rn.f32x2 %0, %1, %2;" : "=l"(d) : "l"(a), "l"(b)); return d;
}
__device__ __forceinline__ ull add2(ull a, ull b) {
    ull d; asm("add.rn.f32x2 %0, %1, %2;" : "=l"(d) : "l"(a), "l"(b)); return d;
}
__device__ __forceinline__ float fast_exp2(float x) {
    float y; asm("ex2.approx.ftz.f32 %0, %1;" : "=f"(y) : "f"(x)); return y;
}

// ---------------------------------------------------------------------------
// 16-dim statevector circuit: qubit q lives at bit (3-q). Fully unrolled;
// CNOTs are free register renames.
// ---------------------------------------------------------------------------
template <int Q>
__device__ __forceinline__ void rx_gate(float sr[16], float si[16], float c, float sn) {
    const int m = 1 << (3 - Q);
#pragma unroll
    for (int i = 0; i < 16; i++) {
        if (!(i & m)) {
            const int j = i | m;
            float a0r = sr[i], a0i = si[i];
            float a1r = sr[j], a1i = si[j];
            sr[i] = c * a0r + sn * a1i;
            si[i] = c * a0i - sn * a1r;
            sr[j] = c * a1r + sn * a0i;
            si[j] = c * a1i - sn * a0r;
        }
    }
}

template <int Q>
__device__ __forceinline__ void cnot_gate(float sr[16], float si[16]) {
    const int cm = 1 << (3 - Q);
    const int tm = 1 << (3 - ((Q + 1) & 3));
#pragma unroll
    for (int i = 0; i < 16; i++) {
        if ((i & cm) && !(i & tm)) {
            const int j = i | tm;
            float t;
            t = sr[i]; sr[i] = sr[j]; sr[j] = t;
            t = si[i]; si[i] = si[j]; si[j] = t;
        }
    }
}

__device__ __forceinline__ float4 measure(const float sr[16], const float si[16]) {
    float e0 = 0.f, e1 = 0.f, e2 = 0.f, e3 = 0.f;
#pragma unroll
    for (int i = 0; i < 16; i++) {
        float p = sr[i] * sr[i] + si[i] * si[i];
        e0 += (i & 8) ? -p : p;
        e1 += (i & 4) ? -p : p;
        e2 += (i & 2) ? -p : p;
        e3 += (i & 1) ? -p : p;
    }
    return make_float4(e0, e1, e2, e3);
}

__device__ __forceinline__ float4 layer_and_measure(
    const float er[16], const float ei[16],
    const float wc[4], const float ws[4])
{
    float sr[16], si[16];
#pragma unroll
    for (int i = 0; i < 16; i++) { sr[i] = er[i]; si[i] = ei[i]; }

    rx_gate<0>(sr, si, wc[0], ws[0]);
    rx_gate<1>(sr, si, wc[1], ws[1]);
    rx_gate<2>(sr, si, wc[2], ws[2]);
    rx_gate<3>(sr, si, wc[3], ws[3]);
    cnot_gate<0>(sr, si);
    cnot_gate<1>(sr, si);
    cnot_gate<2>(sr, si);
    cnot_gate<3>(sr, si);
    return measure(sr, si);
}

// MUFU-based sincos: half-angles are small (x ~ N(0,1)*0.5, ctx in [-0.5,0.5])
// so __sincosf accuracy is far inside the 1e-3 tolerance.
__device__ __forceinline__ void embed(float4 ang, float er[16], float ei[16]) {
#pragma unroll
    for (int i = 0; i < 16; i++) { er[i] = 0.f; ei[i] = 0.f; }
    er[0] = 1.f;
    float c, sn;
    __sincosf(ang.x * 0.5f, &sn, &c); rx_gate<0>(er, ei, c, sn);
    __sincosf(ang.y * 0.5f, &sn, &c); rx_gate<1>(er, ei, c, sn);
    __sincosf(ang.z * 0.5f, &sn, &c); rx_gate<2>(er, ei, c, sn);
    __sincosf(ang.w * 0.5f, &sn, &c); rx_gate<3>(er, ei, c, sn);
}

// Weights: half-angles in [0, pi] — __sincosf abs error far inside tolerance.
__device__ __forceinline__ void load_w(const float* __restrict__ w, float wc[4], float ws[4]) {
#pragma unroll
    for (int i = 0; i < 4; i++) __sincosf(w[i] * 0.5f, &ws[i], &wc[i]);
}

// ---------------------------------------------------------------------------
// Kernel 1: x -> Q (row layout, pre-scaled), K, V (pair-packed layout).
// ---------------------------------------------------------------------------
__global__ void __launch_bounds__(128)
qkv_kernel(const float4* __restrict__ x,
           const float* __restrict__ wQ,
           const float* __restrict__ wK,
           const float* __restrict__ wV)
{
    int idx = blockIdx.x * blockDim.x + threadIdx.x;
    if (idx >= NROWS) return;

    float er[16], ei[16];
    embed(x[idx], er, ei);

    float wc[4], ws[4];
    const float scale = 0.5f * 1.4426950408889634f;  // 1/sqrt(E) * log2(e)
    load_w(wQ, wc, ws);
    {
        float4 qv = layer_and_measure(er, ei, wc, ws);
        qv.x *= scale; qv.y *= scale; qv.z *= scale; qv.w *= scale;
        g_Q[idx] = qv;
    }

    const int p = idx >> 1;
    const int h = idx & 1;
    float* gk = (float*)g_Kp;
    float* gv = (float*)g_Vp;

    load_w(wK, wc, ws);
    {
        float4 k = layer_and_measure(er, ei, wc, ws);
        gk[p * 8 + 0 + h] = k.x;
        gk[p * 8 + 2 + h] = k.y;
        gk[p * 8 + 4 + h] = k.z;
        gk[p * 8 + 6 + h] = k.w;
    }
    load_w(wV, wc, ws);
    {
        float4 v = layer_and_measure(er, ei, wc, ws);
        gv[p * 8 + 0 + h] = v.x;
        gv[p * 8 + 2 + h] = v.y;
        gv[p * 8 + 4 + h] = v.z;
        gv[p * 8 + 6 + h] = v.w;
    }
}

// ---------------------------------------------------------------------------
// Kernel 2: split-K flash attention partials.
// QPT=4 queries/thread: each K/V LDS.128 is amortized over 8 (q,k) pairs
// (0.5 LDS/pair) and each thread carries 4 independent dot->ex2->acc chains
// for ILP. 2 keys per packed f32x2 lane-pair, split-K=16 (2048 blocks).
// Raw exp2 softmax (scores in [-2.9,2.9]): partials combine exactly by sum.
// ---------------------------------------------------------------------------
#define ATTN_TPB   128
#define QPT        4
#define KEYS_SPLIT (SS / NSPLIT)        // 128 keys = 128 packed float4

__global__ void __launch_bounds__(ATTN_TPB)
attn_kernel()
{
    __shared__ float4 sK[KEYS_SPLIT];
    __shared__ float4 sV[KEYS_SPLIT];

    const int b     = blockIdx.y;
    const int split = blockIdx.z;
    const int t     = threadIdx.x;
    const int qrow  = b * SS + blockIdx.x * (ATTN_TPB * QPT) + t;

    // Stage this split's K/V slice.
    if (t < KEYS_SPLIT) {
        sK[t] = g_Kp[b * SS + split * KEYS_SPLIT + t];
        sV[t] = g_Vp[b * SS + split * KEYS_SPLIT + t];
    }

    ull qx[QPT], qy[QPT], qz[QPT], qw[QPT];
#pragma unroll
    for (int j = 0; j < QPT; j++) {
        float4 q = g_Q[qrow + j * ATTN_TPB];
        qx[j] = pack2(q.x, q.x);
        qy[j] = pack2(q.y, q.y);
        qz[j] = pack2(q.z, q.z);
        qw[j] = pack2(q.w, q.w);
    }

    ull den[QPT];
    ull ac0[QPT], ac1[QPT], ac2[QPT], ac3[QPT];
#pragma unroll
    for (int j = 0; j < QPT; j++) {
        den[j] = 0; ac0[j] = 0; ac1[j] = 0; ac2[j] = 0; ac3[j] = 0;
    }

    __syncthreads();

    const ulonglong2* kk = (const ulonglong2*)sK;
    const ulonglong2* vv = (const ulonglong2*)sV;

#pragma unroll 4
    for (int p = 0; p < KEYS_SPLIT / 2; p++) {
        ulonglong2 ka = kk[2 * p];      // (kx pair, ky pair)
        ulonglong2 kb = kk[2 * p + 1];  // (kz pair, kw pair)
        ulonglong2 va = vv[2 * p];
        ulonglong2 vb = vv[2 * p + 1];

#pragma unroll
        for (int j = 0; j < QPT; j++) {
            ull s = fma2(qx[j], ka.x, fma2(qy[j], ka.y,
                     fma2(qz[j], kb.x, mul2(qw[j], kb.y))));
            float s0, s1;
            unpack2(s, s0, s1);
            ull e = pack2(fast_exp2(s0), fast_exp2(s1));

            den[j] = add2(den[j], e);
            ac0[j] = fma2(e, va.x, ac0[j]);
            ac1[j] = fma2(e, va.y, ac1[j]);
            ac2[j] = fma2(e, vb.x, ac2[j]);
            ac3[j] = fma2(e, vb.y, ac3[j]);
        }
    }

    const int base = split * NROWS;
#pragma unroll
    for (int j = 0; j < QPT; j++) {
        float d0, d1, u0, u1;
        float4 num;
        unpack2(ac0[j], u0, u1); num.x = u0 + u1;
        unpack2(ac1[j], u0, u1); num.y = u0 + u1;
        unpack2(ac2[j], u0, u1); num.z = u0 + u1;
        unpack2(ac3[j], u0, u1); num.w = u0 + u1;
        unpack2(den[j], d0, d1);
        g_pnum[base + qrow + j * ATTN_TPB] = num;
        g_pden[base + qrow + j * ATTN_TPB] = d0 + d1;
    }
}

// ---------------------------------------------------------------------------
// Kernel 3: combine split partials -> ctx -> circuit(weights_C) -> out
// ---------------------------------------------------------------------------
__global__ void out_kernel(const float* __restrict__ wC, float4* __restrict__ out)
{
    int idx = blockIdx.x * blockDim.x + threadIdx.x;
    if (idx >= NROWS) return;

    float4 num = g_pnum[idx];
    float  den = g_pden[idx];
#pragma unroll
    for (int s = 1; s < NSPLIT; s++) {
        float4 n = g_pnum[s * NROWS + idx];
        num.x += n.x; num.y += n.y; num.z += n.z; num.w += n.w;
        den += g_pden[s * NROWS + idx];
    }
    float inv = __fdividef(1.f, den);
    float4 ctx = make_float4(num.x * inv, num.y * inv, num.z * inv, num.w * inv);

    float er[16], ei[16];
    embed(ctx, er, ei);

    float wc[4], ws[4];
    load_w(wC, wc, ws);
    out[idx] = layer_and_measure(er, ei, wc, ws);
}

// ---------------------------------------------------------------------------

extern "C" void kernel_launch(void* const* d_in, const int* in_sizes, int n_in,
                              void* d_out, int out_size)
{
    const float4* x  = (const float4*)d_in[0];
    const float*  wQ = (const float*)d_in[1];
    const float*  wK = (const float*)d_in[2];
    const float*  wV = (const float*)d_in[3];
    const float*  wC = (const float*)d_in[4];

    qkv_kernel<<<NROWS / 128, 128>>>(x, wQ, wK, wV);

    dim3 grid(SS / (ATTN_TPB * QPT), BB, NSPLIT);
    attn_kernel<<<grid, ATTN_TPB>>>();

    out_kernel<<<NROWS / 128, 128>>>(wC, (float4*)d_out);
}

// round 12
// speedup vs baseline: 1.0353x; 1.0353x over previous
#include <cuda_runtime.h>

#define BB 32
#define SS 2048
#define NROWS (BB * SS)
#define NSPLIT 16

// Scratch: __device__ globals (no allocation allowed in kernel_launch).
__device__ float4 g_Q[NROWS];            // pre-scaled by 0.5*log2(e)
// Pair-packed layouts: for key pair p (rows 2p, 2p+1):
//   g_Kp[2p]   = (k0.x, k1.x, k0.y, k1.y)
//   g_Kp[2p+1] = (k0.z, k1.z, k0.w, k1.w)
__device__ float4 g_Kp[NROWS];
__device__ float4 g_Vp[NROWS];
__device__ float4 g_pnum[NSPLIT * NROWS];  // partial sum(e*V)
__device__ float  g_pden[NSPLIT * NROWS];  // partial sum(e)

typedef unsigned long long ull;

// ---------------------------------------------------------------------------
// Packed f32x2 helpers (sm_103a FFMA2 path — ptxas won't auto-fuse from C++)
// ---------------------------------------------------------------------------
__device__ __forceinline__ ull pack2(float lo, float hi) {
    ull r; asm("mov.b64 %0, {%1, %2};" : "=l"(r) : "f"(lo), "f"(hi)); return r;
}
__device__ __forceinline__ void unpack2(ull v, float& lo, float& hi) {
    asm("mov.b64 {%0, %1}, %2;" : "=f"(lo), "=f"(hi) : "l"(v));
}
__device__ __forceinline__ ull fma2(ull a, ull b, ull c) {
    ull d; asm("fma.rn.f32x2 %0, %1, %2, %3;" : "=l"(d) : "l"(a), "l"(b), "l"(c)); return d;
}
__device__ __forceinline__ ull mul2(ull a, ull b) {
    ull d; asm("mul.rn.f32x2 %0, %1, %2;" : "=l"(d) : "l"(a), "l"(b)); return d;
}
__device__ __forceinline__ ull add2(ull a, ull b) {
    ull d; asm("add.rn.f32x2 %0, %1, %2;" : "=l"(d) : "l"(a), "l"(b)); return d;
}
__device__ __forceinline__ float fast_exp2(float x) {
    float y; asm("ex2.approx.ftz.f32 %0, %1;" : "=f"(y) : "f"(x)); return y;
}

// ---------------------------------------------------------------------------
// 16-dim statevector circuit: qubit q lives at bit (3-q). Fully unrolled;
// CNOTs are free register renames.
// ---------------------------------------------------------------------------
template <int Q>
__device__ __forceinline__ void rx_gate(float sr[16], float si[16], float c, float sn) {
    const int m = 1 << (3 - Q);
#pragma unroll
    for (int i = 0; i < 16; i++) {
        if (!(i & m)) {
            const int j = i | m;
            float a0r = sr[i], a0i = si[i];
            float a1r = sr[j], a1i = si[j];
            sr[i] = c * a0r + sn * a1i;
            si[i] = c * a0i - sn * a1r;
            sr[j] = c * a1r + sn * a0i;
            si[j] = c * a1i - sn * a0r;
        }
    }
}

template <int Q>
__device__ __forceinline__ void cnot_gate(float sr[16], float si[16]) {
    const int cm = 1 << (3 - Q);
    const int tm = 1 << (3 - ((Q + 1) & 3));
#pragma unroll
    for (int i = 0; i < 16; i++) {
        if ((i & cm) && !(i & tm)) {
            const int j = i | tm;
            float t;
            t = sr[i]; sr[i] = sr[j]; sr[j] = t;
            t = si[i]; si[i] = si[j]; si[j] = t;
        }
    }
}

__device__ __forceinline__ float4 measure(const float sr[16], const float si[16]) {
    float e0 = 0.f, e1 = 0.f, e2 = 0.f, e3 = 0.f;
#pragma unroll
    for (int i = 0; i < 16; i++) {
        float p = sr[i] * sr[i] + si[i] * si[i];
        e0 += (i & 8) ? -p : p;
        e1 += (i & 4) ? -p : p;
        e2 += (i & 2) ? -p : p;
        e3 += (i & 1) ? -p : p;
    }
    return make_float4(e0, e1, e2, e3);
}

__device__ __forceinline__ float4 layer_and_measure(
    const float er[16], const float ei[16],
    const float wc[4], const float ws[4])
{
    float sr[16], si[16];
#pragma unroll
    for (int i = 0; i < 16; i++) { sr[i] = er[i]; si[i] = ei[i]; }

    rx_gate<0>(sr, si, wc[0], ws[0]);
    rx_gate<1>(sr, si, wc[1], ws[1]);
    rx_gate<2>(sr, si, wc[2], ws[2]);
    rx_gate<3>(sr, si, wc[3], ws[3]);
    cnot_gate<0>(sr, si);
    cnot_gate<1>(sr, si);
    cnot_gate<2>(sr, si);
    cnot_gate<3>(sr, si);
    return measure(sr, si);
}

// MUFU-based sincos: half-angles are small (x ~ N(0,1)*0.5, ctx in [-0.5,0.5])
// so __sincosf accuracy is far inside the 1e-3 tolerance.
__device__ __forceinline__ void embed(float4 ang, float er[16], float ei[16]) {
#pragma unroll
    for (int i = 0; i < 16; i++) { er[i] = 0.f; ei[i] = 0.f; }
    er[0] = 1.f;
    float c, sn;
    __sincosf(ang.x * 0.5f, &sn, &c); rx_gate<0>(er, ei, c, sn);
    __sincosf(ang.y * 0.5f, &sn, &c); rx_gate<1>(er, ei, c, sn);
    __sincosf(ang.z * 0.5f, &sn, &c); rx_gate<2>(er, ei, c, sn);
    __sincosf(ang.w * 0.5f, &sn, &c); rx_gate<3>(er, ei, c, sn);
}

// Weights: half-angles in [0, pi] — __sincosf abs error far inside tolerance.
__device__ __forceinline__ void load_w(const float* __restrict__ w, float wc[4], float ws[4]) {
#pragma unroll
    for (int i = 0; i < 4; i++) __sincosf(w[i] * 0.5f, &ws[i], &wc[i]);
}

// ---------------------------------------------------------------------------
// Kernel 1: x -> Q | K | V, one circuit per blockIdx.y.
// The sequential Q+K+V version is grid-limited (65k threads = 14 warps/SM,
// issue 44%); splitting the three circuits across blockIdx.y triples warp
// parallelism (41 warps/SM) for only ~1.1x work (embed recomputed, but embed
// is cheap due to zero propagation from |0>).
// ---------------------------------------------------------------------------
__global__ void __launch_bounds__(128)
qkv_kernel(const float4* __restrict__ x,
           const float* __restrict__ wQ,
           const float* __restrict__ wK,
           const float* __restrict__ wV)
{
    const int idx   = blockIdx.x * blockDim.x + threadIdx.x;
    const int which = blockIdx.y;          // 0=Q, 1=K, 2=V
    if (idx >= NROWS) return;

    float er[16], ei[16];
    embed(x[idx], er, ei);

    const float* w = (which == 0) ? wQ : (which == 1) ? wK : wV;
    float wc[4], ws[4];
    load_w(w, wc, ws);

    float4 r = layer_and_measure(er, ei, wc, ws);

    if (which == 0) {
        const float scale = 0.5f * 1.4426950408889634f;  // 1/sqrt(E)*log2(e)
        r.x *= scale; r.y *= scale; r.z *= scale; r.w *= scale;
        g_Q[idx] = r;
    } else {
        const int p = idx >> 1;
        const int h = idx & 1;
        float* g = (which == 1) ? (float*)g_Kp : (float*)g_Vp;
        g[p * 8 + 0 + h] = r.x;
        g[p * 8 + 2 + h] = r.y;
        g[p * 8 + 4 + h] = r.z;
        g[p * 8 + 6 + h] = r.w;
    }
}

// ---------------------------------------------------------------------------
// Kernel 2: split-K flash attention partials (proven R10 configuration).
// QPT=2 queries/thread, 2 keys per packed f32x2 lane-pair, split-K=16.
// Raw exp2 softmax (scores in [-2.9,2.9]): partials combine exactly by sum.
// ---------------------------------------------------------------------------
#define ATTN_TPB   128
#define KEYS_SPLIT (SS / NSPLIT)        // 128 keys = 128 packed float4

__global__ void __launch_bounds__(ATTN_TPB)
attn_kernel()
{
    __shared__ float4 sK[KEYS_SPLIT];
    __shared__ float4 sV[KEYS_SPLIT];

    const int b     = blockIdx.y;
    const int split = blockIdx.z;
    const int t     = threadIdx.x;
    const int qrow  = b * SS + blockIdx.x * (ATTN_TPB * 2) + t;

    // Stage this split's K/V slice.
    if (t < KEYS_SPLIT) {
        sK[t] = g_Kp[b * SS + split * KEYS_SPLIT + t];
        sV[t] = g_Vp[b * SS + split * KEYS_SPLIT + t];
    }

    float4 qa = g_Q[qrow];
    float4 qb = g_Q[qrow + ATTN_TPB];

    const ull qa_x = pack2(qa.x, qa.x), qa_y = pack2(qa.y, qa.y);
    const ull qa_z = pack2(qa.z, qa.z), qa_w = pack2(qa.w, qa.w);
    const ull qb_x = pack2(qb.x, qb.x), qb_y = pack2(qb.y, qb.y);
    const ull qb_z = pack2(qb.z, qb.z), qb_w = pack2(qb.w, qb.w);

    ull den_a = 0, den_b = 0;
    ull aa0 = 0, aa1 = 0, aa2 = 0, aa3 = 0;
    ull ab0 = 0, ab1 = 0, ab2 = 0, ab3 = 0;

    __syncthreads();

    const ulonglong2* kk = (const ulonglong2*)sK;
    const ulonglong2* vv = (const ulonglong2*)sV;

#pragma unroll 8
    for (int p = 0; p < KEYS_SPLIT / 2; p++) {
        ulonglong2 ka = kk[2 * p];      // (kx pair, ky pair)
        ulonglong2 kb = kk[2 * p + 1];  // (kz pair, kw pair)

        ull sa = fma2(qa_x, ka.x, fma2(qa_y, ka.y, fma2(qa_z, kb.x, mul2(qa_w, kb.y))));
        ull sb = fma2(qb_x, ka.x, fma2(qb_y, ka.y, fma2(qb_z, kb.x, mul2(qb_w, kb.y))));

        float s0, s1;
        unpack2(sa, s0, s1);
        ull ea = pack2(fast_exp2(s0), fast_exp2(s1));
        unpack2(sb, s0, s1);
        ull eb = pack2(fast_exp2(s0), fast_exp2(s1));

        den_a = add2(den_a, ea);
        den_b = add2(den_b, eb);

        ulonglong2 va = vv[2 * p];
        ulonglong2 vb = vv[2 * p + 1];

        aa0 = fma2(ea, va.x, aa0);
        aa1 = fma2(ea, va.y, aa1);
        aa2 = fma2(ea, vb.x, aa2);
        aa3 = fma2(ea, vb.y, aa3);
        ab0 = fma2(eb, va.x, ab0);
        ab1 = fma2(eb, va.y, ab1);
        ab2 = fma2(eb, vb.x, ab2);
        ab3 = fma2(eb, vb.y, ab3);
    }

    const int base = split * NROWS;
    {
        float d0, d1, u0, u1;
        float4 num;
        unpack2(aa0, u0, u1); num.x = u0 + u1;
        unpack2(aa1, u0, u1); num.y = u0 + u1;
        unpack2(aa2, u0, u1); num.z = u0 + u1;
        unpack2(aa3, u0, u1); num.w = u0 + u1;
        unpack2(den_a, d0, d1);
        g_pnum[base + qrow] = num;
        g_pden[base + qrow] = d0 + d1;
    }
    {
        float d0, d1, u0, u1;
        float4 num;
        unpack2(ab0, u0, u1); num.x = u0 + u1;
        unpack2(ab1, u0, u1); num.y = u0 + u1;
        unpack2(ab2, u0, u1); num.z = u0 + u1;
        unpack2(ab3, u0, u1); num.w = u0 + u1;
        unpack2(den_b, d0, d1);
        g_pnum[base + qrow + ATTN_TPB] = num;
        g_pden[base + qrow + ATTN_TPB] = d0 + d1;
    }
}

// ---------------------------------------------------------------------------
// Kernel 3: combine split partials -> ctx -> circuit(weights_C) -> out
// ---------------------------------------------------------------------------
__global__ void out_kernel(const float* __restrict__ wC, float4* __restrict__ out)
{
    int idx = blockIdx.x * blockDim.x + threadIdx.x;
    if (idx >= NROWS) return;

    float4 num = g_pnum[idx];
    float  den = g_pden[idx];
#pragma unroll
    for (int s = 1; s < NSPLIT; s++) {
        float4 n = g_pnum[s * NROWS + idx];
        num.x += n.x; num.y += n.y; num.z += n.z; num.w += n.w;
        den += g_pden[s * NROWS + idx];
    }
    float inv = __fdividef(1.f, den);
    float4 ctx = make_float4(num.x * inv, num.y * inv, num.z * inv, num.w * inv);

    float er[16], ei[16];
    embed(ctx, er, ei);

    float wc[4], ws[4];
    load_w(wC, wc, ws);
    out[idx] = layer_and_measure(er, ei, wc, ws);
}

// ---------------------------------------------------------------------------

extern "C" void kernel_launch(void* const* d_in, const int* in_sizes, int n_in,
                              void* d_out, int out_size)
{
    const float4* x  = (const float4*)d_in[0];
    const float*  wQ = (const float*)d_in[1];
    const float*  wK = (const float*)d_in[2];
    const float*  wV = (const float*)d_in[3];
    const float*  wC = (const float*)d_in[4];

    dim3 qkv_grid(NROWS / 128, 3);
    qkv_kernel<<<qkv_grid, 128>>>(x, wQ, wK, wV);

    dim3 grid(SS / (ATTN_TPB * 2), BB, NSPLIT);
    attn_kernel<<<grid, ATTN_TPB>>>();

    out_kernel<<<NROWS / 128, 128>>>(wC, (float4*)d_out);
}